// round 5
// baseline (speedup 1.0000x reference)
#include <cuda_runtime.h>
#include <cstdint>
#include <cstddef>

// Problem constants
#define NUM_LUT 3
#define GDIM    1024      // G = IN_F / VEC
#define OUTF    4096
#define SLUT    16
#define VEC     4
#define NGRP    32        // NG = IN_F / GROUP (GROUP = 32 g's)

// Tiling: block = 8 warps; each warp owns 8 consecutive o's; block loops 16 g's.
#define NTHREADS 256
#define O_PER_WARP 8
#define OTILE (8 * O_PER_WARP)   // 64 o per block
#define GTILE_J 16               // g's per block (16 | 32 -> single quant group per block)

// Per-LUT processing: local argmax-of-4, quad bfly merge with exact
// first-index tie-break (bit-exact vs jnp.argmax), codebook gather of
// this lane's component.
#define DO_LUT(v, L, g, accv)                                              \
    {                                                                      \
        float m = (v).x; int mi = 0;                                       \
        if ((v).y > m) { m = (v).y; mi = 1; }                              \
        if ((v).z > m) { m = (v).z; mi = 2; }                              \
        if ((v).w > m) { m = (v).w; mi = 3; }                              \
        mi += part * 4;                                                    \
        _Pragma("unroll")                                                  \
        for (int d = 1; d <= 2; d <<= 1) {                                 \
            float om = __shfl_xor_sync(0xffffffffu, m,  d);                \
            int   oi = __shfl_xor_sync(0xffffffffu, mi, d);                \
            if (om > m || (om == m && oi < mi)) { m = om; mi = oi; }       \
        }                                                                  \
        (accv) += __ldg(cbk + (((size_t)(L) * GDIM + (g)) * SLUT + mi) * VEC + part); \
    }

__global__ void __launch_bounds__(NTHREADS)
recon_kernel(const float* __restrict__ gate,
             const float* __restrict__ codebook,
             const float* __restrict__ scales,
             const int*   __restrict__ zeros,
             float*       __restrict__ out)
{
    const int tid    = threadIdx.x;
    const int wid    = tid >> 5;
    const int lane   = tid & 31;
    const int part   = lane & 3;          // which 16B quarter of the 64B gate row
    const int o_sub  = lane >> 2;         // which of the warp's 8 o's
    (void)o_sub;

    const int o0     = blockIdx.x * OTILE + wid * O_PER_WARP;  // warp's first o
    const int o      = o0 + (lane >> 2);
    const int g0     = blockIdx.y * GTILE_J;
    const int ng     = blockIdx.y >> 1;   // quant group (16*2 = 32 g's per group)

    const float sc = scales[o * NGRP + ng];
    const float zz = (float)zeros[o * NGRP + ng];

    // Gate base pointers (float4 units). For fixed (l,g): warp covers
    // o0..o0+7 -> 512B contiguous; lane q reads float4 #q.
    const float4* gp0 = reinterpret_cast<const float4*>(gate) +
        (((size_t)0 * GDIM + g0) * OUTF + o0) * (SLUT / 4) + lane;
    const float4* gp1 = reinterpret_cast<const float4*>(gate) +
        (((size_t)1 * GDIM + g0) * OUTF + o0) * (SLUT / 4) + lane;
    const float4* gp2 = reinterpret_cast<const float4*>(gate) +
        (((size_t)2 * GDIM + g0) * OUTF + o0) * (SLUT / 4) + lane;
    const size_t gstep = (size_t)OUTF * SLUT / 4;   // 16384 float4 per g

    const float* cbk = codebook;

    float* outrow = out + (size_t)o * (GDIM * VEC) + part;  // + g*4 per step

    // ---- software pipeline: always keep the NEXT g's 3 loads in flight ----
    float4 c0 = __ldcs(gp0);
    float4 c1 = __ldcs(gp1);
    float4 c2 = __ldcs(gp2);

    #pragma unroll 5
    for (int j = 0; j < GTILE_J - 1; ++j) {
        // prefetch j+1 (independent of everything below)
        const float4 n0 = __ldcs(gp0 + (size_t)(j + 1) * gstep);
        const float4 n1 = __ldcs(gp1 + (size_t)(j + 1) * gstep);
        const float4 n2 = __ldcs(gp2 + (size_t)(j + 1) * gstep);

        const int g = g0 + j;
        float acc = 0.0f;
        DO_LUT(c0, 0, g, acc)
        DO_LUT(c1, 1, g, acc)
        DO_LUT(c2, 2, g, acc)
        __stcs(outrow + g * VEC, (acc - zz) * sc);

        c0 = n0; c1 = n1; c2 = n2;
    }

    // epilogue: last g
    {
        const int g = g0 + GTILE_J - 1;
        float acc = 0.0f;
        DO_LUT(c0, 0, g, acc)
        DO_LUT(c1, 1, g, acc)
        DO_LUT(c2, 2, g, acc)
        __stcs(outrow + g * VEC, (acc - zz) * sc);
    }
}

extern "C" void kernel_launch(void* const* d_in, const int* in_sizes, int n_in,
                              void* d_out, int out_size) {
    const float* gate     = (const float*)d_in[0];  // [3,1024,4096,16] f32
    const float* codebook = (const float*)d_in[1];  // [3,1024,16,4]   f32
    const float* scales   = (const float*)d_in[2];  // [4096,32]       f32
    const int*   zeros    = (const int*)  d_in[3];  // [4096,32]       i32
    float*       out      = (float*)d_out;          // [4096,4096]     f32

    (void)in_sizes; (void)n_in; (void)out_size;

    dim3 grid(OUTF / OTILE, GDIM / GTILE_J);   // (64, 64) = 4096 blocks
    recon_kernel<<<grid, NTHREADS>>>(gate, codebook, scales, zeros, out);
}